// round 14
// baseline (speedup 1.0000x reference)
#include <cuda_runtime.h>
#include <cuda_fp16.h>
#include <cstdint>

#define BB 4096
#define TT 512
#define DD 8
#define HH 64
#define TB 32
#define NT 512

// smem layout: B0, B1 weight tiles + double-buffered A operands (256B rows, XOR-16B swizzle)
#define SB0 0            // B0: 256 rows (k: [Wih0 0..7][b0 @8][0][Whh0 16..79][0..])  64KB
#define SB1 65536        // B1: 256 rows (k: [Wih1 0..63][Whh1 64..127])               64KB
#define SA0P(p) (131072 + (p) * 8192)  // A0 bufs: 32 rows (k: [x|1|pad|h0])
#define SA1P(p) (147456 + (p) * 8192)  // A1 bufs: 32 rows (k: [h0|h1])
#define SMEM_TOTAL 163840

static __device__ __forceinline__ uint32_t smem_u32(const void* p){
    uint32_t a;
    asm("{ .reg .u64 t; cvta.to.shared.u64 t, %1; cvt.u32.u64 %0, t; }" : "=r"(a) : "l"(p));
    return a;
}
static __device__ __forceinline__ uint32_t swb(int row, int kb){
    return (uint32_t)(row * 256 + ((((kb) >> 4) ^ (row & 7)) << 4) + ((kb) & 15));
}
static __device__ __forceinline__ float tanha(float x){
    float y; asm("tanh.approx.f32 %0, %1;" : "=f"(y) : "f"(x)); return y;
}
static __device__ __forceinline__ uint32_t pack2(float a, float b){
    __half2 h = __floats2half2_rn(a, b);
    return *(uint32_t*)&h;
}

#define LDSM4(addr, r0, r1, r2, r3) \
    asm volatile("ldmatrix.sync.aligned.m8n8.x4.shared.b16 {%0,%1,%2,%3}, [%4];" \
        : "=r"(r0), "=r"(r1), "=r"(r2), "=r"(r3) : "r"(addr))
#define LDSM2(addr, r0, r1) \
    asm volatile("ldmatrix.sync.aligned.m8n8.x2.shared.b16 {%0,%1}, [%2];" \
        : "=r"(r0), "=r"(r1) : "r"(addr))
#define MMA(accp, ap, b0_, b1_) \
    asm volatile("mma.sync.aligned.m16n8k16.row.col.f32.f16.f16.f32 " \
        "{%0,%1,%2,%3},{%4,%5,%6,%7},{%8,%9},{%0,%1,%2,%3};" \
        : "+f"((accp)[0]), "+f"((accp)[1]), "+f"((accp)[2]), "+f"((accp)[3]) \
        : "r"((ap)[0]), "r"((ap)[1]), "r"((ap)[2]), "r"((ap)[3]), "r"(b0_), "r"(b1_))

// Preload this warp's B fragments for its [64 x 16*KTILES] weight tile into registers.
template<int KTILES>
static __device__ __forceinline__ void preload_B(uint32_t bbase, int nbase, int lane,
                                                 uint32_t bw[8][8][2])
{
    const int bl  = lane & 7;
    const int bco = lane >> 3;
    #pragma unroll
    for (int nt = 0; nt < 8; nt++) {
        const int brow = nbase + 8 * nt + bl;
        const uint32_t brb = bbase + (uint32_t)(brow * 256);
        const int brx = brow & 7;
        #pragma unroll
        for (int ktp = 0; ktp < KTILES / 2; ktp++) {
            uint32_t bd = brb + (uint32_t)(((4 * ktp + bco) ^ brx) << 4);
            LDSM4(bd, bw[nt][2 * ktp][0], bw[nt][2 * ktp][1],
                      bw[nt][2 * ktp + 1][0], bw[nt][2 * ktp + 1][1]);
        }
        if (KTILES & 1) {
            const int kt = KTILES - 1;
            uint32_t bd = brb + (uint32_t)(((2 * kt + (bco & 1)) ^ brx) << 4);
            LDSM2(bd, bw[nt][kt][0], bw[nt][kt][1]);
        }
    }
}

// gemm with register-resident B: loads only A fragments from smem.
template<int KTILES>
static __device__ __forceinline__ void gemm_regB(uint32_t abase, int m0, int lane,
                                                 const uint32_t bw[8][8][2],
                                                 float acc[8][4])
{
    const int amat = lane >> 3;
    const int arow = m0 + (lane & 7) + (amat & 1) * 8;
    const uint32_t arb = abase + (uint32_t)(arow * 256);
    const int arx = arow & 7;
    const int apc = amat >> 1;
    if constexpr (KTILES <= 5) {
        uint32_t af[KTILES][4];
        #pragma unroll
        for (int kt = 0; kt < KTILES; kt++) {
            uint32_t ad = arb + (uint32_t)(((2 * kt + apc) ^ arx) << 4);
            LDSM4(ad, af[kt][0], af[kt][1], af[kt][2], af[kt][3]);
        }
        #pragma unroll
        for (int nt = 0; nt < 8; nt++)
            #pragma unroll
            for (int kt = 0; kt < KTILES; kt++)
                MMA(acc[nt], af[kt], bw[nt][kt][0], bw[nt][kt][1]);
    } else {
        // two halves of 4 k-tiles: caps A-frag registers at 16.
        // Per-accumulator k order (0..7) unchanged -> bit-identical results.
        #pragma unroll
        for (int h = 0; h < 2; h++) {
            uint32_t af[4][4];
            #pragma unroll
            for (int k = 0; k < 4; k++) {
                const int kt = 4 * h + k;
                uint32_t ad = arb + (uint32_t)(((2 * kt + apc) ^ arx) << 4);
                LDSM4(ad, af[k][0], af[k][1], af[k][2], af[k][3]);
            }
            #pragma unroll
            for (int nt = 0; nt < 8; nt++)
                #pragma unroll
                for (int k = 0; k < 4; k++)
                    MMA(acc[nt], af[k], bw[nt][4 * h + k][0], bw[nt][4 * h + k][1]);
        }
    }
}

// column permutation (64-col period): n = 64*blk + 32*gp + 8*j + pos
//   u = 16*blk + 4*j + (pos>>1),  g = 2*gp + (pos&1)
static __device__ __forceinline__ void decode_n(int n, int& u, int& g){
    int blk = n >> 6, w64 = n & 63;
    int gp = w64 >> 5, rem = w64 & 31;
    int j = rem >> 3, pos = rem & 7;
    u = (blk << 4) + (j << 2) + (pos >> 1);
    g = (gp << 1) + (pos & 1);
}

__global__ void __launch_bounds__(NT, 1)
lstm_mma(const float* __restrict__ x,
         const float* __restrict__ Wih0, const float* __restrict__ Whh0,
         const float* __restrict__ bih0, const float* __restrict__ bhh0,
         const float* __restrict__ Wih1, const float* __restrict__ Whh1,
         const float* __restrict__ bih1, const float* __restrict__ bhh1,
         const float* __restrict__ Wfc,  const float* __restrict__ bfc,
         float* __restrict__ out)
{
    extern __shared__ char sm[];
    const uint32_t sbase = smem_u32(sm);
    const int tid = threadIdx.x, lane = tid & 31, w = tid >> 5;
    const int r = lane >> 2, cc = lane & 3;
    const bool isL0 = (w < 8);
    const int wl = isL0 ? w : (w - 8);
    const int m0 = 16 * (wl & 1);   // M tile rows
    const int q  = wl >> 1;         // 64-col block (0..3)
    const int U0 = 16 * q;          // unit base
    const int nbase = 64 * q;       // B row base
    const int b0g = blockIdx.x * TB;

    // zero all 4 A buffers (32KB)
    for (int i = tid; i < 2048; i += NT)
        ((uint4*)(sm + SA0P(0)))[i] = make_uint4(0, 0, 0, 0);

    // B0: [Wih0 | b0 | 0 | Whh0 | 0], permuted rows, swizzled
    for (int idx = tid; idx < 256 * 128; idx += NT) {
        int n = idx >> 7, k = idx & 127;
        int u, g; decode_n(n, u, g);
        int sr = g * 64 + u;
        float v = 0.f;
        if (k < 8)                  v = Wih0[sr * DD + k];
        else if (k == 8)            v = bih0[sr] + bhh0[sr];
        else if (k >= 16 && k < 80) v = Whh0[sr * HH + (k - 16)];
        *(__half*)(sm + SB0 + swb(n, 2 * k)) = __float2half_rn(v);
    }
    // B1: [Wih1 | Whh1]
    for (int idx = tid; idx < 256 * 128; idx += NT) {
        int n = idx >> 7, k = idx & 127;
        int u, g; decode_n(n, u, g);
        int sr = g * 64 + u;
        float v = (k < 64) ? Wih1[sr * HH + k] : Whh1[sr * HH + (k - 64)];
        *(__half*)(sm + SB1 + swb(n, 2 * k)) = __float2half_rn(v);
    }

    // bias1 in regs (0.5-prescaled for sigmoid gates) — L1 warps only
    float bi05[4], bf05[4], bg1[4], bo05[4];
    if (!isL0) {
        #pragma unroll
        for (int j = 0; j < 4; j++) {
            int u = U0 + 4 * j + cc;
            bi05[j] = 0.5f * (bih1[u]       + bhh1[u]);
            bf05[j] = 0.5f * (bih1[64 + u]  + bhh1[64 + u]);
            bg1[j]  =        (bih1[128 + u] + bhh1[128 + u]);
            bo05[j] = 0.5f * (bih1[192 + u] + bhh1[192 + u]);
        }
    }
    __syncthreads();

    // Preload this warp's loop-invariant B fragments into registers.
    uint32_t bw[8][8][2];
    if (isL0) preload_B<5>(sbase + SB0, nbase, lane, bw);
    else      preload_B<8>(sbase + SB1, nbase, lane, bw);

    // const-1 column (k=8) in BOTH A0 buffers + x_0 into A0 buf 0
    if (tid < TB) {
        *(__half*)(sm + SA0P(0) + swb(tid, 16)) = __float2half_rn(1.0f);
        *(__half*)(sm + SA0P(1) + swb(tid, 16)) = __float2half_rn(1.0f);
        const float* xp = x + (size_t)(b0g + tid) * TT * DD;
        float4 xa = ((const float4*)xp)[0], xb = ((const float4*)xp)[1];
        uint4 v;
        v.x = pack2(xa.x, xa.y); v.y = pack2(xa.z, xa.w);
        v.z = pack2(xb.x, xb.y); v.w = pack2(xb.z, xb.w);
        *(uint4*)(sm + SA0P(0) + (uint32_t)(tid * 256 + ((tid & 7) << 4))) = v;
    }
    __syncthreads();

    float cs[8];
    #pragma unroll
    for (int i = 0; i < 8; i++) cs[i] = 0.f;
    float acc[8][4];
    float4 xa, xb;

    // Pipelined: L0 computes step i, L1 computes step i-1 (epilogue at i-2).
    for (int i = 0; i <= TT + 1; i++) {
        const int pA = i & 1;

        // ---------- phase A: L0 gemm(step i)  ||  L1 epilogue(step i-2) ----------
        if (isL0) {
            if (i < TT) {
                if (w == 0 && i + 1 < TT) {   // prefetch x_{i+1}, hidden under gemm
                    const float* xp = x + (size_t)(b0g + lane) * TT * DD + (size_t)(i + 1) * DD;
                    xa = ((const float4*)xp)[0]; xb = ((const float4*)xp)[1];
                }
                #pragma unroll
                for (int nt = 0; nt < 8; nt++)
                    { acc[nt][0] = 0.f; acc[nt][1] = 0.f; acc[nt][2] = 0.f; acc[nt][3] = 0.f; }
                gemm_regB<5>(sbase + SA0P(pA), m0, lane, bw, acc);
            }
        } else {
            if (i >= 2) {
                const uint32_t dstH1 = (uint32_t)SA1P((i - 1) & 1);
                #pragma unroll
                for (int j = 0; j < 4; j++) {
                    #pragma unroll
                    for (int rh = 0; rh < 2; rh++) {
                        float zi = acc[j][rh * 2],     zf = acc[j][rh * 2 + 1];
                        float zg = acc[4 + j][rh * 2], zo = acc[4 + j][rh * 2 + 1];
                        float I = 0.5f * tanha(0.5f * zi + bi05[j]) + 0.5f;
                        float F = 0.5f * tanha(0.5f * zf + bf05[j]) + 0.5f;
                        float G = tanha(zg + bg1[j]);
                        float O = 0.5f * tanha(0.5f * zo + bo05[j]) + 0.5f;
                        int ci = j * 2 + rh;
                        float cn = F * cs[ci] + I * G;
                        cs[ci] = cn;
                        float h = O * tanha(cn);
                        int u = U0 + 4 * j + cc;
                        int row = m0 + r + rh * 8;
                        *(__half*)(sm + dstH1 + swb(row, 2 * (64 + u))) = __float2half_rn(h);
                    }
                }
            }
        }
        __syncthreads();

        // ---------- phase B: L0 epilogue(step i)  ||  L1 gemm(step i-1) ----------
        if (isL0) {
            if (i < TT) {
                if (w == 0 && i + 1 < TT) {
                    uint4 v;
                    v.x = pack2(xa.x, xa.y); v.y = pack2(xa.z, xa.w);
                    v.z = pack2(xb.x, xb.y); v.w = pack2(xb.z, xb.w);
                    *(uint4*)(sm + SA0P(pA ^ 1) + (uint32_t)(lane * 256 + ((lane & 7) << 4))) = v;
                }
                const uint32_t oA0 = (uint32_t)SA0P(pA ^ 1);
                const uint32_t oA1 = (uint32_t)SA1P(pA);
                #pragma unroll
                for (int j = 0; j < 4; j++) {
                    #pragma unroll
                    for (int rh = 0; rh < 2; rh++) {
                        float zi = acc[j][rh * 2],     zf = acc[j][rh * 2 + 1];
                        float zg = acc[4 + j][rh * 2], zo = acc[4 + j][rh * 2 + 1];
                        float I = 0.5f * tanha(0.5f * zi) + 0.5f;
                        float F = 0.5f * tanha(0.5f * zf) + 0.5f;
                        float G = tanha(zg);
                        float O = 0.5f * tanha(0.5f * zo) + 0.5f;
                        int ci = j * 2 + rh;
                        float cn = F * cs[ci] + I * G;
                        cs[ci] = cn;
                        float h = O * tanha(cn);
                        int u = U0 + 4 * j + cc;
                        int row = m0 + r + rh * 8;
                        __half hh = __float2half_rn(h);
                        *(__half*)(sm + oA0 + swb(row, 2 * (16 + u))) = hh;  // L0 recurrence
                        *(__half*)(sm + oA1 + swb(row, 2 * u)) = hh;         // L1 input
                    }
                }
            }
        } else {
            if (i >= 1 && i <= TT) {
                #pragma unroll
                for (int nt = 0; nt < 8; nt++)
                    { acc[nt][0] = 0.f; acc[nt][1] = 0.f; acc[nt][2] = 0.f; acc[nt][3] = 0.f; }
                gemm_regB<8>(sbase + SA1P((i - 1) & 1), m0, lane, bw, acc);
            }
        }
        __syncthreads();
    }

    // final FC: h1_{511} lives in A1 buf[0] (k 64..127)
    if (tid < TB) {
        float s = bfc[0];
        #pragma unroll 8
        for (int u = 0; u < HH; u++)
            s += __half2float(*(const __half*)(sm + SA1P(0) + swb(tid, 2 * (64 + u)))) * Wfc[u];
        out[b0g + tid] = s;
    }
}

extern "C" void kernel_launch(void* const* d_in, const int* in_sizes, int n_in,
                              void* d_out, int out_size)
{
    (void)in_sizes; (void)n_in; (void)out_size;
    cudaFuncSetAttribute(lstm_mma, cudaFuncAttributeMaxDynamicSharedMemorySize, SMEM_TOTAL);
    lstm_mma<<<BB / TB, NT, SMEM_TOTAL>>>(
        (const float*)d_in[0],
        (const float*)d_in[1], (const float*)d_in[2],
        (const float*)d_in[3], (const float*)d_in[4],
        (const float*)d_in[5], (const float*)d_in[6],
        (const float*)d_in[7], (const float*)d_in[8],
        (const float*)d_in[9], (const float*)d_in[10],
        (float*)d_out);
}

// round 15
// speedup vs baseline: 2.1110x; 2.1110x over previous
#include <cuda_runtime.h>
#include <cuda_fp16.h>
#include <cstdint>

#define BB 4096
#define TT 512
#define DD 8
#define HH 64
#define TB 32
#define NT 256

// smem layout: B0, B1 weight tiles + double-buffered A operands (256B rows, XOR-16B swizzle)
#define SB0 0            // B0: 256 rows (k: [Wih0 0..7][b0 @8][0][Whh0 16..79][0..])  64KB
#define SB1 65536        // B1: 256 rows (k: [Wih1 0..63][Whh1 64..127])               64KB
#define SA0P(p) (131072 + (p) * 8192)  // A0 bufs: 32 rows (k: [x|1|pad|h0])
#define SA1P(p) (147456 + (p) * 8192)  // A1 bufs: 32 rows (k: [h0|h1])
#define SBIAS 163840     // 256 f32: prescaled bias1 [gate][unit]
#define SMEM_TOTAL 164864

static __device__ __forceinline__ uint32_t smem_u32(const void* p){
    uint32_t a;
    asm("{ .reg .u64 t; cvta.to.shared.u64 t, %1; cvt.u32.u64 %0, t; }" : "=r"(a) : "l"(p));
    return a;
}
static __device__ __forceinline__ uint32_t swb(int row, int kb){
    return (uint32_t)(row * 256 + ((((kb) >> 4) ^ (row & 7)) << 4) + ((kb) & 15));
}
static __device__ __forceinline__ float tanha(float x){
    float y; asm("tanh.approx.f32 %0, %1;" : "=f"(y) : "f"(x)); return y;
}
static __device__ __forceinline__ uint32_t pack2(float a, float b){
    __half2 h = __floats2half2_rn(a, b);
    return *(uint32_t*)&h;
}

#define LDSM4(addr, r0, r1, r2, r3) \
    asm volatile("ldmatrix.sync.aligned.m8n8.x4.shared.b16 {%0,%1,%2,%3}, [%4];" \
        : "=r"(r0), "=r"(r1), "=r"(r2), "=r"(r3) : "r"(addr))
#define LDSM2(addr, r0, r1) \
    asm volatile("ldmatrix.sync.aligned.m8n8.x2.shared.b16 {%0,%1}, [%2];" \
        : "=r"(r0), "=r"(r1) : "r"(addr))
#define MMA(accp, ap, b0_, b1_) \
    asm volatile("mma.sync.aligned.m16n8k16.row.col.f32.f16.f16.f32 " \
        "{%0,%1,%2,%3},{%4,%5,%6,%7},{%8,%9},{%0,%1,%2,%3};" \
        : "+f"((accp)[0]), "+f"((accp)[1]), "+f"((accp)[2]), "+f"((accp)[3]) \
        : "r"((ap)[0]), "r"((ap)[1]), "r"((ap)[2]), "r"((ap)[3]), "r"(b0_), "r"(b1_))

// Preload this warp's B fragments (64 n-rows x 16*KTILES k) into registers.
template<int KTILES>
static __device__ __forceinline__ void preload_B(uint32_t bbase, int nbase, int lane,
                                                 uint32_t bw[8][8][2])
{
    const int bl  = lane & 7;
    const int bco = lane >> 3;
    #pragma unroll
    for (int nt = 0; nt < 8; nt++) {
        const int brow = nbase + 8 * nt + bl;
        const uint32_t brb = bbase + (uint32_t)(brow * 256);
        const int brx = brow & 7;
        #pragma unroll
        for (int ktp = 0; ktp < KTILES / 2; ktp++) {
            uint32_t bd = brb + (uint32_t)(((4 * ktp + bco) ^ brx) << 4);
            LDSM4(bd, bw[nt][2 * ktp][0], bw[nt][2 * ktp][1],
                      bw[nt][2 * ktp + 1][0], bw[nt][2 * ktp + 1][1]);
        }
        if (KTILES & 1) {
            const int kt = KTILES - 1;
            uint32_t bd = brb + (uint32_t)(((2 * kt + (bco & 1)) ^ brx) << 4);
            LDSM2(bd, bw[nt][kt][0], bw[nt][kt][1]);
        }
    }
}

// 32-row x 64-col gemm with register-resident B; A fragments from smem in 4-kt chunks.
template<int KTILES>
static __device__ __forceinline__ void gemm_regB(uint32_t abase, int lane,
                                                 const uint32_t (&bw)[8][8][2],
                                                 float acc[2][8][4])
{
    const int amat = lane >> 3;
    const int alow = (lane & 7) + (amat & 1) * 8;
    const int apc = amat >> 1;
    #pragma unroll
    for (int mt = 0; mt < 2; mt++) {
        const int arow = mt * 16 + alow;
        const uint32_t arb = abase + (uint32_t)(arow * 256);
        const int arx = arow & 7;
        constexpr int NCH = (KTILES + 3) / 4;
        #pragma unroll
        for (int ch = 0; ch < NCH; ch++) {
            constexpr int CH_K = 4;
            const int kbeg = ch * CH_K;
            const int kcnt = (KTILES - kbeg < CH_K) ? (KTILES - kbeg) : CH_K;
            uint32_t af[CH_K][4];
            #pragma unroll
            for (int k = 0; k < CH_K; k++) {
                if (k < kcnt) {
                    const int kt = kbeg + k;
                    uint32_t ad = arb + (uint32_t)(((2 * kt + apc) ^ arx) << 4);
                    LDSM4(ad, af[k][0], af[k][1], af[k][2], af[k][3]);
                }
            }
            #pragma unroll
            for (int nt = 0; nt < 8; nt++)
                #pragma unroll
                for (int k = 0; k < CH_K; k++)
                    if (k < kcnt)
                        MMA(acc[mt][nt], af[k], bw[nt][kbeg + k][0], bw[nt][kbeg + k][1]);
        }
    }
}

// column permutation (64-col period): n = 64*blk + 32*gp + 8*j + pos
//   u = 16*blk + 4*j + (pos>>1),  g = 2*gp + (pos&1)
static __device__ __forceinline__ void decode_n(int n, int& u, int& g){
    int blk = n >> 6, w64 = n & 63;
    int gp = w64 >> 5, rem = w64 & 31;
    int j = rem >> 3, pos = rem & 7;
    u = (blk << 4) + (j << 2) + (pos >> 1);
    g = (gp << 1) + (pos & 1);
}

__global__ void __launch_bounds__(NT, 1)
lstm_mma(const float* __restrict__ x,
         const float* __restrict__ Wih0, const float* __restrict__ Whh0,
         const float* __restrict__ bih0, const float* __restrict__ bhh0,
         const float* __restrict__ Wih1, const float* __restrict__ Whh1,
         const float* __restrict__ bih1, const float* __restrict__ bhh1,
         const float* __restrict__ Wfc,  const float* __restrict__ bfc,
         float* __restrict__ out)
{
    extern __shared__ char sm[];
    const uint32_t sbase = smem_u32(sm);
    const int tid = threadIdx.x, lane = tid & 31, w = tid >> 5;
    const int r = lane >> 2, cc = lane & 3;
    const bool isL0 = (w < 4);
    const int q = w & 3;            // 64-col block (0..3)
    const int U0 = 16 * q;          // unit base
    const int nbase = 64 * q;       // B row base
    const int b0g = blockIdx.x * TB;

    // zero all 4 A buffers (32KB)
    for (int i = tid; i < 2048; i += NT)
        ((uint4*)(sm + SA0P(0)))[i] = make_uint4(0, 0, 0, 0);

    // B0: [Wih0 | b0 | 0 | Whh0 | 0], permuted rows, swizzled
    for (int idx = tid; idx < 256 * 128; idx += NT) {
        int n = idx >> 7, k = idx & 127;
        int u, g; decode_n(n, u, g);
        int sr = g * 64 + u;
        float v = 0.f;
        if (k < 8)                  v = Wih0[sr * DD + k];
        else if (k == 8)            v = bih0[sr] + bhh0[sr];
        else if (k >= 16 && k < 80) v = Whh0[sr * HH + (k - 16)];
        *(__half*)(sm + SB0 + swb(n, 2 * k)) = __float2half_rn(v);
    }
    // B1: [Wih1 | Whh1]
    for (int idx = tid; idx < 256 * 128; idx += NT) {
        int n = idx >> 7, k = idx & 127;
        int u, g; decode_n(n, u, g);
        int sr = g * 64 + u;
        float v = (k < 64) ? Wih1[sr * HH + k] : Whh1[sr * HH + (k - 64)];
        *(__half*)(sm + SB1 + swb(n, 2 * k)) = __float2half_rn(v);
    }
    // prescaled bias1 in smem: sbias[g*64+u], factor 0.5 for sigmoid gates (i,f,o), 1.0 for g
    for (int idx = tid; idx < 256; idx += NT) {
        int g = idx >> 6;
        float f = (g == 2) ? 1.0f : 0.5f;
        ((float*)(sm + SBIAS))[idx] = f * (bih1[idx] + bhh1[idx]);
    }
    __syncthreads();

    // Preload this warp's loop-invariant B fragments into registers.
    uint32_t bw[8][8][2];
    if (isL0) preload_B<5>(sbase + SB0, nbase, lane, bw);
    else      preload_B<8>(sbase + SB1, nbase, lane, bw);

    // const-1 column (k=8) in BOTH A0 buffers + x_0 into A0 buf 0
    if (tid < TB) {
        *(__half*)(sm + SA0P(0) + swb(tid, 16)) = __float2half_rn(1.0f);
        *(__half*)(sm + SA0P(1) + swb(tid, 16)) = __float2half_rn(1.0f);
        const float* xp = x + (size_t)(b0g + tid) * TT * DD;
        float4 xa = ((const float4*)xp)[0], xb = ((const float4*)xp)[1];
        uint4 v;
        v.x = pack2(xa.x, xa.y); v.y = pack2(xa.z, xa.w);
        v.z = pack2(xb.x, xb.y); v.w = pack2(xb.z, xb.w);
        *(uint4*)(sm + SA0P(0) + (uint32_t)(tid * 256 + ((tid & 7) << 4))) = v;
    }
    __syncthreads();

    const float* sbias = (const float*)(sm + SBIAS);

    float cs[16];   // cs[mt*8 + j*2 + rh]
    #pragma unroll
    for (int i = 0; i < 16; i++) cs[i] = 0.f;
    float acc[2][8][4];
    float4 xa, xb;

    // Pipelined: L0 computes step i, L1 computes step i-1 (epilogue at i-2).
    for (int i = 0; i <= TT + 1; i++) {
        const int pA = i & 1;

        // ---------- phase A: L0 gemm(step i)  ||  L1 epilogue(step i-2) ----------
        if (isL0) {
            if (i < TT) {
                if (w == 0 && i + 1 < TT) {   // prefetch x_{i+1}, hidden under gemm
                    const float* xp = x + (size_t)(b0g + lane) * TT * DD + (size_t)(i + 1) * DD;
                    xa = ((const float4*)xp)[0]; xb = ((const float4*)xp)[1];
                }
                #pragma unroll
                for (int mt = 0; mt < 2; mt++)
                    #pragma unroll
                    for (int nt = 0; nt < 8; nt++)
                        { acc[mt][nt][0] = 0.f; acc[mt][nt][1] = 0.f;
                          acc[mt][nt][2] = 0.f; acc[mt][nt][3] = 0.f; }
                gemm_regB<5>(sbase + SA0P(pA), lane, bw, acc);
            }
        } else {
            if (i >= 2) {
                const uint32_t dstH1 = (uint32_t)SA1P((i - 1) & 1);
                #pragma unroll
                for (int j = 0; j < 4; j++) {
                    const int u = U0 + 4 * j + cc;
                    const float bi05 = sbias[u],        bf05 = sbias[64 + u];
                    const float bg1  = sbias[128 + u],  bo05 = sbias[192 + u];
                    #pragma unroll
                    for (int mt = 0; mt < 2; mt++) {
                        #pragma unroll
                        for (int rh = 0; rh < 2; rh++) {
                            float zi = acc[mt][j][rh * 2],     zf = acc[mt][j][rh * 2 + 1];
                            float zg = acc[mt][4 + j][rh * 2], zo = acc[mt][4 + j][rh * 2 + 1];
                            float I = 0.5f * tanha(0.5f * zi + bi05) + 0.5f;
                            float F = 0.5f * tanha(0.5f * zf + bf05) + 0.5f;
                            float G = tanha(zg + bg1);
                            float O = 0.5f * tanha(0.5f * zo + bo05) + 0.5f;
                            int ci = mt * 8 + j * 2 + rh;
                            float cn = F * cs[ci] + I * G;
                            cs[ci] = cn;
                            float h = O * tanha(cn);
                            int row = mt * 16 + r + rh * 8;
                            *(__half*)(sm + dstH1 + swb(row, 2 * (64 + u))) = __float2half_rn(h);
                        }
                    }
                }
            }
        }
        __syncthreads();

        // ---------- phase B: L0 epilogue(step i)  ||  L1 gemm(step i-1) ----------
        if (isL0) {
            if (i < TT) {
                if (w == 0 && i + 1 < TT) {
                    uint4 v;
                    v.x = pack2(xa.x, xa.y); v.y = pack2(xa.z, xa.w);
                    v.z = pack2(xb.x, xb.y); v.w = pack2(xb.z, xb.w);
                    *(uint4*)(sm + SA0P(pA ^ 1) + (uint32_t)(lane * 256 + ((lane & 7) << 4))) = v;
                }
                const uint32_t oA0 = (uint32_t)SA0P(pA ^ 1);
                const uint32_t oA1 = (uint32_t)SA1P(pA);
                #pragma unroll
                for (int j = 0; j < 4; j++) {
                    const int u = U0 + 4 * j + cc;
                    #pragma unroll
                    for (int mt = 0; mt < 2; mt++) {
                        #pragma unroll
                        for (int rh = 0; rh < 2; rh++) {
                            float zi = acc[mt][j][rh * 2],     zf = acc[mt][j][rh * 2 + 1];
                            float zg = acc[mt][4 + j][rh * 2], zo = acc[mt][4 + j][rh * 2 + 1];
                            float I = 0.5f * tanha(0.5f * zi) + 0.5f;
                            float F = 0.5f * tanha(0.5f * zf) + 0.5f;
                            float G = tanha(zg);
                            float O = 0.5f * tanha(0.5f * zo) + 0.5f;
                            int ci = mt * 8 + j * 2 + rh;
                            float cn = F * cs[ci] + I * G;
                            cs[ci] = cn;
                            float h = O * tanha(cn);
                            int row = mt * 16 + r + rh * 8;
                            __half hh = __float2half_rn(h);
                            *(__half*)(sm + oA0 + swb(row, 2 * (16 + u))) = hh;  // L0 recurrence
                            *(__half*)(sm + oA1 + swb(row, 2 * u)) = hh;         // L1 input
                        }
                    }
                }
            }
        } else {
            if (i >= 1 && i <= TT) {
                #pragma unroll
                for (int mt = 0; mt < 2; mt++)
                    #pragma unroll
                    for (int nt = 0; nt < 8; nt++)
                        { acc[mt][nt][0] = 0.f; acc[mt][nt][1] = 0.f;
                          acc[mt][nt][2] = 0.f; acc[mt][nt][3] = 0.f; }
                gemm_regB<8>(sbase + SA1P((i - 1) & 1), lane, bw, acc);
            }
        }
        __syncthreads();
    }

    // final FC: h1_{511} lives in A1 buf[0] (k 64..127)
    if (tid < TB) {
        float s = bfc[0];
        #pragma unroll 8
        for (int u = 0; u < HH; u++)
            s += __half2float(*(const __half*)(sm + SA1P(0) + swb(tid, 2 * (64 + u)))) * Wfc[u];
        out[b0g + tid] = s;
    }
}

extern "C" void kernel_launch(void* const* d_in, const int* in_sizes, int n_in,
                              void* d_out, int out_size)
{
    (void)in_sizes; (void)n_in; (void)out_size;
    cudaFuncSetAttribute(lstm_mma, cudaFuncAttributeMaxDynamicSharedMemorySize, SMEM_TOTAL);
    lstm_mma<<<BB / TB, NT, SMEM_TOTAL>>>(
        (const float*)d_in[0],
        (const float*)d_in[1], (const float*)d_in[2],
        (const float*)d_in[3], (const float*)d_in[4],
        (const float*)d_in[5], (const float*)d_in[6],
        (const float*)d_in[7], (const float*)d_in[8],
        (const float*)d_in[9], (const float*)d_in[10],
        (float*)d_out);
}